// round 16
// baseline (speedup 1.0000x reference)
#include <cuda_runtime.h>
#include <cuda_fp16.h>
#include <cstdint>

// ---------------------------------------------------------------------------
// Problem constants
// ---------------------------------------------------------------------------
#define N_IN    8192
#define N_OUT   256
#define BATCH   1024
#define LEVELS  2
#define NKSTEPS (LEVELS * N_IN)               // 16384 ; kstep = (l,i), 16 k each
#define KSPLIT  18
#define KSTEPS_PER 912                        // even per split: 17*912 + 880
#define MTILES  (BATCH / 64)                  // 16  (CTA M = 64)

// main-kernel pipeline: stage = full 8KB B tile + 512B (v,h) slice
#define STAGES   6
#define STAGE_B  (8192 + 512)
#define SMEM_BYTES (STAGES * STAGE_B)         // 52224 (dynamic, 2 CTAs/SM)

// Scratch (__device__ globals: no runtime allocation)
// g_B[kstep][j][p] : p = permuted truth-table index so lane t's uint2 at byte
//                    8t is exactly the mma.m16n8k16 B fragment (b0,b1).
__device__ __half   g_B  [(size_t)NKSTEPS * N_OUT * 16];      // 134 MB
__device__ unsigned g_mc0[(size_t)LEVELS * BATCH * N_IN];     // [l][b][i] tmp
// mcT2[l][i][bperm] = (v, h); uint4 view = rows (g, g+8) of an m16 block.
__device__ uint4    g_mcT2[(size_t)LEVELS * N_IN * BATCH / 2];  // 134 MB
__device__ float    g_part[(size_t)KSPLIT * BATCH * N_OUT];   // split-K partials

// ---------------------------------------------------------------------------
// prep_B: for kstep (l,i), thread j:  s[c] = sign(w[16l+c,i,j]) * mask[i,j]
// stored in permuted order {0,1,8,9, 2,3,10,11, 4,5,12,13, 6,7,14,15}.
// ---------------------------------------------------------------------------
__global__ void __launch_bounds__(256) prep_B_kernel(const float* __restrict__ w,
                                                     const float* __restrict__ mask) {
    const int ki = blockIdx.x;               // l*8192 + i
    const int l  = ki >> 13;
    const int i  = ki & (N_IN - 1);
    const int j  = threadIdx.x;
    const float m = mask[(size_t)i * N_OUT + j];
    float s[16];
#pragma unroll
    for (int c = 0; c < 16; ++c) {
        float v = w[((size_t)(16 * l + c) * N_IN + i) * N_OUT + j];
        s[c] = (v > 0.f) ? m : ((v < 0.f) ? -m : 0.f);
    }
    const int perm[16] = {0, 1, 8, 9, 2, 3, 10, 11, 4, 5, 12, 13, 6, 7, 14, 15};
    unsigned r[8];
#pragma unroll
    for (int p = 0; p < 8; ++p) {
        unsigned lo = __half_as_ushort(__float2half_rn(s[perm[2 * p]]));
        unsigned hi = __half_as_ushort(__float2half_rn(s[perm[2 * p + 1]]));
        r[p] = lo | (hi << 16);
    }
    uint4* d = (uint4*)(g_B + ((size_t)ki * N_OUT + j) * 16);
    d[0] = make_uint4(r[0], r[1], r[2], r[3]);
    d[1] = make_uint4(r[4], r[5], r[6], r[7]);
}

// ---------------------------------------------------------------------------
// prep_x: mc0[l][b][i] = (c<<16) | fp16(|s0*s1*s2*s3|)
// x-row staged in SMEM so the 3 random gathers are LDS, not fragmented L1tex.
// ---------------------------------------------------------------------------
__global__ void __launch_bounds__(256) prep_x_kernel(const float* __restrict__ x,
                                                     const int* __restrict__ rm0,
                                                     const int* __restrict__ rm1,
                                                     const int* __restrict__ rm2) {
    __shared__ float srow[N_IN];                    // 32 KB
    const int lb = blockIdx.x;
    const float* row = x + (size_t)lb * N_IN;
    for (int i = threadIdx.x; i < N_IN; i += 256)
        srow[i] = row[i];
    __syncthreads();

    unsigned* mp = g_mc0 + (size_t)lb * N_IN;
    for (int i = threadIdx.x; i < N_IN; i += 256) {
        float s0 = srow[i];
        float s1 = srow[rm0[i]];
        float s2 = srow[rm1[i]];
        float s3 = srow[rm2[i]];
        unsigned c = ((s0 < 0.f) ? 8u : 0u) | ((s1 < 0.f) ? 4u : 0u) |
                     ((s2 < 0.f) ? 2u : 0u) | ((s3 < 0.f) ? 1u : 0u);
        unsigned mh = __half_as_ushort(__float2half_rn(fabsf(s0 * s1 * s2 * s3)));
        mp[i] = (c << 16) | mh;
    }
}

// ---------------------------------------------------------------------------
// transpose mc0 [l][b][i] -> mcT2 [l][i][bperm] = (v, h),
//   v = mag placed in fp16x2 half (c&1), h = c>>1  (A-gen precompute)
// bperm = (b&~15) | ((b&7)<<1) | ((b>>3)&1)  (rows g and g+8 adjacent, so one
// aligned uint4 = both (v,h) pairs of an m16 block)
// ---------------------------------------------------------------------------
__global__ void __launch_bounds__(256) transpose_mc_kernel() {
    __shared__ unsigned tile[32][33];
    const int l  = blockIdx.z;
    const int b0 = blockIdx.y * 32;
    const int i0 = blockIdx.x * 32;
    const int tx = threadIdx.x, ty = threadIdx.y;
#pragma unroll
    for (int r = ty; r < 32; r += 8)
        tile[r][tx] = g_mc0[((size_t)l * BATCH + b0 + r) * N_IN + i0 + tx];
    __syncthreads();
    uint2* mcT2v = (uint2*)g_mcT2;
#pragma unroll
    for (int r = ty; r < 32; r += 8) {
        int b  = b0 + tx;
        int bp = (b & ~15) | ((b & 7) << 1) | ((b >> 3) & 1);
        unsigned w  = tile[tx][r];
        unsigned c  = w >> 16, mh = w & 0xFFFFu;
        uint2 vh;
        vh.x = (c & 1u) ? (mh << 16) : mh;
        vh.y = c >> 1;
        mcT2v[((size_t)l * N_IN + i0 + r) * BATCH + bp] = vh;
    }
}

// ---------------------------------------------------------------------------
// HMMA main kernel — R15 pipeline, warp tile 64(M) x 32(N): warp = warp_n,
// each warp owns all 64 M-rows and a disjoint 32-col B slice, so the 8KB B
// tile is read from smem exactly ONCE per kstep (was 2x).
// grid = (MTILES=16, KSPLIT=18); block = 256 (8 warps, 2 CTAs/SM).
// 2 ksteps per barrier; 6 stages.
// ---------------------------------------------------------------------------
__device__ __forceinline__ uint32_t smem_u32(const void* p) {
    return (uint32_t)__cvta_generic_to_shared(p);
}
#define CP_ASYNC16(dst, src) \
    asm volatile("cp.async.cg.shared.global [%0], [%1], 16;" :: "r"(dst), "l"(src) : "memory")
#define CP_COMMIT() asm volatile("cp.async.commit_group;" ::: "memory")
#define CP_WAIT(n)  asm volatile("cp.async.wait_group %0;" :: "n"(n) : "memory")

__device__ __forceinline__ void mma16816(float* d, unsigned a0, unsigned a1,
                                         unsigned a2, unsigned a3,
                                         unsigned b0, unsigned b1) {
    asm volatile(
        "mma.sync.aligned.m16n8k16.row.col.f32.f16.f16.f32 "
        "{%0,%1,%2,%3}, {%4,%5,%6,%7}, {%8,%9}, {%0,%1,%2,%3};"
        : "+f"(d[0]), "+f"(d[1]), "+f"(d[2]), "+f"(d[3])
        : "r"(a0), "r"(a1), "r"(a2), "r"(a3), "r"(b0), "r"(b1));
}

__global__ void __launch_bounds__(256, 2) main_kernel() {
    extern __shared__ __align__(16) unsigned char sm[];
    const uint32_t smb = smem_u32(sm);

    const int tid  = threadIdx.x;
    const int warp = tid >> 5, lane = tid & 31;    // warp = warp_n (0..7)
    const int g = lane >> 2, t = lane & 3;
    const int bm0 = blockIdx.x * 64;                 // CTA batch-row base
    const int jn  = warp * 32;                       // warp out-col base
    const int ks0 = blockIdx.y * KSTEPS_PER;
    const int nk  = min(NKSTEPS - ks0, KSTEPS_PER);  // always even

    float acc[4][4][4];                              // [m16 blk][n8 frag][4]
#pragma unroll
    for (int a = 0; a < 4; ++a)
#pragma unroll
        for (int b = 0; b < 4; ++b)
#pragma unroll
            for (int d = 0; d < 4; ++d) acc[a][b][d] = 0.f;

    // producer addresses: B tile 8KB = 256 thr x 32B (2x16B);
    // (v,h) slice 512B = 32 thr x 16B.
    const char* srcB0 = (const char*)g_B + (size_t)ks0 * 8192 + tid * 32;
    const char* srcM0 = (const char*)g_mcT2
                      + (((size_t)ks0 * BATCH + bm0) << 3) + tid * 16;

    auto fill = [&](int it) {
        if (it < nk) {
            uint32_t st = smb + (it % STAGES) * STAGE_B;
            const char* sB = srcB0 + (size_t)it * 8192;
            CP_ASYNC16(st + tid * 32, sB);
            CP_ASYNC16(st + tid * 32 + 16, sB + 16);
            if (tid < 32)
                CP_ASYNC16(st + 8192 + tid * 16, srcM0 + ((size_t)it * BATCH << 3));
        }
        CP_COMMIT();
    };

    // prologue: fill ksteps 0..3 (4 groups in flight)
#pragma unroll
    for (int p = 0; p < 4; ++p) fill(p);

    // consumer smem offsets: B rows jn..jn+31 (disjoint per warp);
    // Mc blocks 0..3 (broadcast across warps), uint4 index blk*8+g.
    const uint32_t bOff = ((uint32_t)(jn + g) << 5) + ((uint32_t)t << 3);
    const uint32_t mOff = 8192u + ((uint32_t)g << 4);

    auto consume = [&](int it) {                     // load frags + 16 HMMA
        const uint32_t st = smb + (it % STAGES) * STAGE_B;
        uint2 B[4];
#pragma unroll
        for (int f = 0; f < 4; ++f)
            asm volatile("ld.shared.v2.u32 {%0,%1}, [%2];"
                         : "=r"(B[f].x), "=r"(B[f].y) : "r"(st + bOff + f * 256));
        uint4 Mc[4];
#pragma unroll
        for (int blk = 0; blk < 4; ++blk)
            asm volatile("ld.shared.v4.u32 {%0,%1,%2,%3}, [%4];"
                         : "=r"(Mc[blk].x), "=r"(Mc[blk].y),
                           "=r"(Mc[blk].z), "=r"(Mc[blk].w)
                         : "r"(st + mOff + blk * 128));
        fill(it + 4);                                // refill while MMAs run
#pragma unroll
        for (int blk = 0; blk < 4; ++blk) {
            const uint4 m = Mc[blk];                 // v0,h0,v1,h1 (rows g,g+8)
            unsigned a0 = (m.y == (unsigned)t)       ? m.x : 0u;
            unsigned a1 = (m.w == (unsigned)t)       ? m.z : 0u;
            unsigned a2 = (m.y == (unsigned)(t + 4)) ? m.x : 0u;
            unsigned a3 = (m.w == (unsigned)(t + 4)) ? m.z : 0u;
#pragma unroll
            for (int f = 0; f < 4; ++f)
                mma16816(acc[blk][f], a0, a1, a2, a3, B[f].x, B[f].y);
        }
    };

    // main loop: 2 ksteps per barrier.  CP_WAIT(2) -> stages it, it+1 resident
    // (fills it+2, it+3 still pending).  Slot disjointness mod 6: writes
    // (it+4, it+5) vs reads (it, it+1) differ by >=3.
    for (int it = 0; it < nk; it += 2) {
        CP_WAIT(2);
        __syncthreads();
        consume(it);
        consume(it + 1);
    }

    // Epilogue: split-K partial tile (no atomics).
    float* pp = g_part + (size_t)blockIdx.y * BATCH * N_OUT;
#pragma unroll
    for (int blk = 0; blk < 4; ++blk) {
        int r0 = bm0 + blk * 16 + g, r1 = r0 + 8;
#pragma unroll
        for (int f = 0; f < 4; ++f) {
            int j0 = jn + f * 8 + 2 * t;
            *(float2*)&pp[(size_t)r0 * N_OUT + j0] =
                make_float2(acc[blk][f][0], acc[blk][f][1]);
            *(float2*)&pp[(size_t)r1 * N_OUT + j0] =
                make_float2(acc[blk][f][2], acc[blk][f][3]);
        }
    }
}

// ---------------------------------------------------------------------------
// reduce: out = |gamma| * sum over KSPLIT partials
// ---------------------------------------------------------------------------
__global__ void __launch_bounds__(256) reduce_kernel(const float* __restrict__ gamma,
                                                     float* __restrict__ out) {
    size_t idx = (size_t)blockIdx.x * 256 + threadIdx.x;
    float s = 0.f;
#pragma unroll
    for (int p = 0; p < KSPLIT; ++p)
        s += g_part[(size_t)p * BATCH * N_OUT + idx];
    out[idx] = s * fabsf(gamma[0]);
}

// ---------------------------------------------------------------------------
// launch — inputs: x f32[2,1024,8192], w f32[32,8192,256], gamma f32[1],
// pruning_mask f32[8192,256], rand_map_0/1/2 i32[8192]. out f32[1024,256].
// ---------------------------------------------------------------------------
extern "C" void kernel_launch(void* const* d_in, const int* in_sizes, int n_in,
                              void* d_out, int out_size) {
    const float* x     = (const float*)d_in[0];
    const float* w     = (const float*)d_in[1];
    const float* gamma = (const float*)d_in[2];
    const float* mask  = (const float*)d_in[3];
    const int*   rm0   = (const int*)d_in[4];
    const int*   rm1   = (const int*)d_in[5];
    const int*   rm2   = (const int*)d_in[6];
    float* out = (float*)d_out;

    prep_B_kernel<<<NKSTEPS, 256>>>(w, mask);
    prep_x_kernel<<<LEVELS * BATCH, 256>>>(x, rm0, rm1, rm2);
    transpose_mc_kernel<<<dim3(N_IN / 32, BATCH / 32, LEVELS), dim3(32, 8)>>>();

    cudaFuncSetAttribute(main_kernel, cudaFuncAttributeMaxDynamicSharedMemorySize,
                         SMEM_BYTES);
    main_kernel<<<dim3(MTILES, KSPLIT), 256, SMEM_BYTES>>>();
    reduce_kernel<<<(BATCH * N_OUT) / 256, 256>>>(gamma, out);
}

// round 17
// speedup vs baseline: 1.1202x; 1.1202x over previous
#include <cuda_runtime.h>
#include <cuda_fp16.h>
#include <cstdint>

// ---------------------------------------------------------------------------
// Problem constants
// ---------------------------------------------------------------------------
#define N_IN    8192
#define N_OUT   256
#define BATCH   1024
#define LEVELS  2
#define NKSTEPS (LEVELS * N_IN)               // 16384 ; kstep = (l,i), 16 k each
#define KSPLIT  18
#define KSTEPS_PER 912                        // even per split: 17*912 + 880
#define MTILES  (BATCH / 64)                  // 16  (CTA M = 64)

// main-kernel pipeline: stage = full 8KB B tile + 512B (v,h) slice
#define STAGES   6
#define STAGE_B  (8192 + 512)
#define SMEM_BYTES (STAGES * STAGE_B)         // 52224 (dynamic, 2 CTAs/SM)

// Scratch (__device__ globals: no runtime allocation)
// g_B[kstep][j][p] : p = permuted truth-table index so lane t's uint2 at byte
//                    8t is exactly the mma.m16n8k16 B fragment (b0,b1).
__device__ __half   g_B  [(size_t)NKSTEPS * N_OUT * 16];      // 134 MB
__device__ unsigned g_mc0[(size_t)LEVELS * BATCH * N_IN];     // [l][b][i] tmp
// mcT2[l][i][bperm] = (v, h); uint4 view = rows (g, g+8) of an m16 block.
__device__ uint4    g_mcT2[(size_t)LEVELS * N_IN * BATCH / 2];  // 134 MB
__device__ float    g_part[(size_t)KSPLIT * BATCH * N_OUT];   // split-K partials

// ---------------------------------------------------------------------------
// prep_B: for kstep (l,i), thread j:  s[c] = sign(w[16l+c,i,j]) * mask[i,j]
// stored in permuted order {0,1,8,9, 2,3,10,11, 4,5,12,13, 6,7,14,15}.
// ---------------------------------------------------------------------------
__global__ void __launch_bounds__(256) prep_B_kernel(const float* __restrict__ w,
                                                     const float* __restrict__ mask) {
    const int ki = blockIdx.x;               // l*8192 + i
    const int l  = ki >> 13;
    const int i  = ki & (N_IN - 1);
    const int j  = threadIdx.x;
    const float m = mask[(size_t)i * N_OUT + j];
    float s[16];
#pragma unroll
    for (int c = 0; c < 16; ++c) {
        float v = w[((size_t)(16 * l + c) * N_IN + i) * N_OUT + j];
        s[c] = (v > 0.f) ? m : ((v < 0.f) ? -m : 0.f);
    }
    const int perm[16] = {0, 1, 8, 9, 2, 3, 10, 11, 4, 5, 12, 13, 6, 7, 14, 15};
    unsigned r[8];
#pragma unroll
    for (int p = 0; p < 8; ++p) {
        unsigned lo = __half_as_ushort(__float2half_rn(s[perm[2 * p]]));
        unsigned hi = __half_as_ushort(__float2half_rn(s[perm[2 * p + 1]]));
        r[p] = lo | (hi << 16);
    }
    uint4* d = (uint4*)(g_B + ((size_t)ki * N_OUT + j) * 16);
    d[0] = make_uint4(r[0], r[1], r[2], r[3]);
    d[1] = make_uint4(r[4], r[5], r[6], r[7]);
}

// ---------------------------------------------------------------------------
// prep_x: mc0[l][b][i] = (c<<16) | fp16(|s0*s1*s2*s3|)
// x-row staged in SMEM so the 3 random gathers are LDS, not fragmented L1tex.
// ---------------------------------------------------------------------------
__global__ void __launch_bounds__(256) prep_x_kernel(const float* __restrict__ x,
                                                     const int* __restrict__ rm0,
                                                     const int* __restrict__ rm1,
                                                     const int* __restrict__ rm2) {
    __shared__ float srow[N_IN];                    // 32 KB
    const int lb = blockIdx.x;
    const float* row = x + (size_t)lb * N_IN;
    for (int i = threadIdx.x; i < N_IN; i += 256)
        srow[i] = row[i];
    __syncthreads();

    unsigned* mp = g_mc0 + (size_t)lb * N_IN;
    for (int i = threadIdx.x; i < N_IN; i += 256) {
        float s0 = srow[i];
        float s1 = srow[rm0[i]];
        float s2 = srow[rm1[i]];
        float s3 = srow[rm2[i]];
        unsigned c = ((s0 < 0.f) ? 8u : 0u) | ((s1 < 0.f) ? 4u : 0u) |
                     ((s2 < 0.f) ? 2u : 0u) | ((s3 < 0.f) ? 1u : 0u);
        unsigned mh = __half_as_ushort(__float2half_rn(fabsf(s0 * s1 * s2 * s3)));
        mp[i] = (c << 16) | mh;
    }
}

// ---------------------------------------------------------------------------
// transpose mc0 [l][b][i] -> mcT2 [l][i][bperm] = (v, h),
//   v = mag placed in fp16x2 half (c&1), h = c>>1  (A-gen precompute)
// bperm = (b&~15) | ((b&7)<<1) | ((b>>3)&1)  (rows g and g+8 adjacent, so one
// aligned uint4 = both (v,h) pairs of an m16 block)
// ---------------------------------------------------------------------------
__global__ void __launch_bounds__(256) transpose_mc_kernel() {
    __shared__ unsigned tile[32][33];
    const int l  = blockIdx.z;
    const int b0 = blockIdx.y * 32;
    const int i0 = blockIdx.x * 32;
    const int tx = threadIdx.x, ty = threadIdx.y;
#pragma unroll
    for (int r = ty; r < 32; r += 8)
        tile[r][tx] = g_mc0[((size_t)l * BATCH + b0 + r) * N_IN + i0 + tx];
    __syncthreads();
    uint2* mcT2v = (uint2*)g_mcT2;
#pragma unroll
    for (int r = ty; r < 32; r += 8) {
        int b  = b0 + tx;
        int bp = (b & ~15) | ((b & 7) << 1) | ((b >> 3) & 1);
        unsigned w  = tile[tx][r];
        unsigned c  = w >> 16, mh = w & 0xFFFFu;
        uint2 vh;
        vh.x = (c & 1u) ? (mh << 16) : mh;
        vh.y = c >> 1;
        mcT2v[((size_t)l * N_IN + i0 + r) * BATCH + bp] = vh;
    }
}

// ---------------------------------------------------------------------------
// HMMA main kernel — R15 structure with the kstep pair software-pipelined:
// after each barrier, fragments for BOTH ksteps are loaded (and A selected)
// before any MMA issues, so the second kstep's LDS latency hides under the
// first kstep's tensor work.
// grid = (MTILES=16, KSPLIT=18); block = 256 (8 warps, 2 CTAs/SM).
// CTA tile M=64 x N=256; warp tile 32(M) x 64(N) (warp_m=warp&1, warp_n=warp>>1).
// ---------------------------------------------------------------------------
__device__ __forceinline__ uint32_t smem_u32(const void* p) {
    return (uint32_t)__cvta_generic_to_shared(p);
}
#define CP_ASYNC16(dst, src) \
    asm volatile("cp.async.cg.shared.global [%0], [%1], 16;" :: "r"(dst), "l"(src) : "memory")
#define CP_COMMIT() asm volatile("cp.async.commit_group;" ::: "memory")
#define CP_WAIT(n)  asm volatile("cp.async.wait_group %0;" :: "n"(n) : "memory")

__device__ __forceinline__ void mma16816(float* d, unsigned a0, unsigned a1,
                                         unsigned a2, unsigned a3,
                                         unsigned b0, unsigned b1) {
    asm volatile(
        "mma.sync.aligned.m16n8k16.row.col.f32.f16.f16.f32 "
        "{%0,%1,%2,%3}, {%4,%5,%6,%7}, {%8,%9}, {%0,%1,%2,%3};"
        : "+f"(d[0]), "+f"(d[1]), "+f"(d[2]), "+f"(d[3])
        : "r"(a0), "r"(a1), "r"(a2), "r"(a3), "r"(b0), "r"(b1));
}

__global__ void __launch_bounds__(256, 2) main_kernel() {
    extern __shared__ __align__(16) unsigned char sm[];
    const uint32_t smb = smem_u32(sm);

    const int tid  = threadIdx.x;
    const int warp = tid >> 5, lane = tid & 31;
    const int g = lane >> 2, t = lane & 3;
    const int warp_m = warp & 1, warp_n = warp >> 1;
    const int bm0 = blockIdx.x * 64;                 // CTA batch-row base
    const int jn  = warp_n * 64;                     // warp out-col base
    const int ks0 = blockIdx.y * KSTEPS_PER;
    const int nk  = min(NKSTEPS - ks0, KSTEPS_PER);  // always even

    float acc[2][8][4];
#pragma unroll
    for (int a = 0; a < 2; ++a)
#pragma unroll
        for (int b = 0; b < 8; ++b)
#pragma unroll
            for (int d = 0; d < 4; ++d) acc[a][b][d] = 0.f;

    // producer addresses: B tile 8KB = 256 thr x 32B (2x16B);
    // (v,h) slice 512B = 32 thr x 16B.
    const char* srcB0 = (const char*)g_B + (size_t)ks0 * 8192 + tid * 32;
    const char* srcM0 = (const char*)g_mcT2
                      + (((size_t)ks0 * BATCH + bm0) << 3) + tid * 16;

    auto fill = [&](int it) {
        if (it < nk) {
            uint32_t st = smb + (it % STAGES) * STAGE_B;
            const char* sB = srcB0 + (size_t)it * 8192;
            CP_ASYNC16(st + tid * 32, sB);
            CP_ASYNC16(st + tid * 32 + 16, sB + 16);
            if (tid < 32)
                CP_ASYNC16(st + 8192 + tid * 16, srcM0 + ((size_t)it * BATCH << 3));
        }
        CP_COMMIT();
    };

    // prologue: fill ksteps 0..3 (4 groups in flight)
#pragma unroll
    for (int p = 0; p < 4; ++p) fill(p);

    // consumer smem offsets
    const uint32_t bOff = ((uint32_t)(jn + g) << 5) + ((uint32_t)t << 3);
    const uint32_t mOff = 8192u + (((uint32_t)warp_m * 16 + g) << 4);

    // load B frags + Mc, select A immediately (frees Mc registers)
    auto loadfr = [&](int it, uint2* B, unsigned A[2][4]) {
        const uint32_t st = smb + (it % STAGES) * STAGE_B;
#pragma unroll
        for (int f = 0; f < 8; ++f)
            asm volatile("ld.shared.v2.u32 {%0,%1}, [%2];"
                         : "=r"(B[f].x), "=r"(B[f].y) : "r"(st + bOff + f * 256));
#pragma unroll
        for (int blk = 0; blk < 2; ++blk) {
            uint4 m;
            asm volatile("ld.shared.v4.u32 {%0,%1,%2,%3}, [%4];"
                         : "=r"(m.x), "=r"(m.y), "=r"(m.z), "=r"(m.w)
                         : "r"(st + mOff + blk * 128));
            A[blk][0] = (m.y == (unsigned)t)       ? m.x : 0u;
            A[blk][1] = (m.w == (unsigned)t)       ? m.z : 0u;
            A[blk][2] = (m.y == (unsigned)(t + 4)) ? m.x : 0u;
            A[blk][3] = (m.w == (unsigned)(t + 4)) ? m.z : 0u;
        }
    };

    auto mmaall = [&](unsigned A[2][4], const uint2* B) {
#pragma unroll
        for (int blk = 0; blk < 2; ++blk)
#pragma unroll
            for (int f = 0; f < 8; ++f)
                mma16816(acc[blk][f], A[blk][0], A[blk][1], A[blk][2], A[blk][3],
                         B[f].x, B[f].y);
    };

    // main loop: 2 ksteps per barrier; both ksteps' fragments loaded before
    // any MMA so LDS/select latency of kstep it+1 hides under MMAs of it.
    // CP_WAIT(2) -> stages it, it+1 resident; fills (it+4, it+5) write slots
    // >= 3 away mod 6 from the slots being read.
    for (int it = 0; it < nk; it += 2) {
        CP_WAIT(2);
        __syncthreads();

        uint2    B0[8], B1[8];
        unsigned A0[2][4], A1[2][4];
        loadfr(it,     B0, A0);
        loadfr(it + 1, B1, A1);

        fill(it + 4);
        fill(it + 5);

        mmaall(A0, B0);
        mmaall(A1, B1);
    }

    // Epilogue: split-K partial tile (no atomics).
    float* pp = g_part + (size_t)blockIdx.y * BATCH * N_OUT;
#pragma unroll
    for (int blk = 0; blk < 2; ++blk) {
        int r0 = bm0 + warp_m * 32 + blk * 16 + g, r1 = r0 + 8;
#pragma unroll
        for (int f = 0; f < 8; ++f) {
            int j0 = jn + f * 8 + 2 * t;
            *(float2*)&pp[(size_t)r0 * N_OUT + j0] =
                make_float2(acc[blk][f][0], acc[blk][f][1]);
            *(float2*)&pp[(size_t)r1 * N_OUT + j0] =
                make_float2(acc[blk][f][2], acc[blk][f][3]);
        }
    }
}

// ---------------------------------------------------------------------------
// reduce: out = |gamma| * sum over KSPLIT partials
// ---------------------------------------------------------------------------
__global__ void __launch_bounds__(256) reduce_kernel(const float* __restrict__ gamma,
                                                     float* __restrict__ out) {
    size_t idx = (size_t)blockIdx.x * 256 + threadIdx.x;
    float s = 0.f;
#pragma unroll
    for (int p = 0; p < KSPLIT; ++p)
        s += g_part[(size_t)p * BATCH * N_OUT + idx];
    out[idx] = s * fabsf(gamma[0]);
}

// ---------------------------------------------------------------------------
// launch — inputs: x f32[2,1024,8192], w f32[32,8192,256], gamma f32[1],
// pruning_mask f32[8192,256], rand_map_0/1/2 i32[8192]. out f32[1024,256].
// ---------------------------------------------------------------------------
extern "C" void kernel_launch(void* const* d_in, const int* in_sizes, int n_in,
                              void* d_out, int out_size) {
    const float* x     = (const float*)d_in[0];
    const float* w     = (const float*)d_in[1];
    const float* gamma = (const float*)d_in[2];
    const float* mask  = (const float*)d_in[3];
    const int*   rm0   = (const int*)d_in[4];
    const int*   rm1   = (const int*)d_in[5];
    const int*   rm2   = (const int*)d_in[6];
    float* out = (float*)d_out;

    prep_B_kernel<<<NKSTEPS, 256>>>(w, mask);
    prep_x_kernel<<<LEVELS * BATCH, 256>>>(x, rm0, rm1, rm2);
    transpose_mc_kernel<<<dim3(N_IN / 32, BATCH / 32, LEVELS), dim3(32, 8)>>>();

    cudaFuncSetAttribute(main_kernel, cudaFuncAttributeMaxDynamicSharedMemorySize,
                         SMEM_BYTES);
    main_kernel<<<dim3(MTILES, KSPLIT), 256, SMEM_BYTES>>>();
    reduce_kernel<<<(BATCH * N_OUT) / 256, 256>>>(gamma, out);
}